// round 1
// baseline (speedup 1.0000x reference)
#include <cuda_runtime.h>
#include <math.h>

#define AA 3072   // A = BS * IA
#define DD 2048   // D = BS * (IA-1)
#define NB 1024   // BS

// scratch ping-pong buffers (no device allocation allowed)
__device__ float g_buf0[AA];
__device__ float g_buf1[AA];

// ---------------------------------------------------------------------------
// GEMV: y[row] = act( dot(W[row,:], x) + b[row] )
// Warp-per-row, x staged in shared memory, float4 fully-unrolled loads.
// ACT: 0 = none, 1 = tanh, 2 = tanhshrink (h - tanh(h))
// ---------------------------------------------------------------------------
template<int ACT, int COLS>
__global__ void __launch_bounds__(256) gemv_kernel(const float* __restrict__ W,
                                                   const float* __restrict__ x,
                                                   const float* __restrict__ b,
                                                   float* __restrict__ y)
{
    __shared__ float sx[COLS];
    for (int t = threadIdx.x; t < COLS; t += 256) sx[t] = x[t];
    __syncthreads();

    const int warp = threadIdx.x >> 5;
    const int lane = threadIdx.x & 31;
    const int row  = blockIdx.x * 8 + warp;

    const float4* __restrict__ W4 =
        reinterpret_cast<const float4*>(W + (size_t)row * COLS);
    const float4* __restrict__ x4 = reinterpret_cast<const float4*>(sx);

    constexpr int N4 = COLS / 4;       // 768 or 512 (multiple of 32)
    float acc0 = 0.f, acc1 = 0.f;
    #pragma unroll
    for (int k = lane; k < N4; k += 32) {
        float4 w = W4[k];
        float4 v = x4[k];
        acc0 = fmaf(w.x, v.x, acc0);
        acc1 = fmaf(w.y, v.y, acc1);
        acc0 = fmaf(w.z, v.z, acc0);
        acc1 = fmaf(w.w, v.w, acc1);
    }
    float acc = acc0 + acc1;
    #pragma unroll
    for (int off = 16; off; off >>= 1)
        acc += __shfl_xor_sync(0xFFFFFFFFu, acc, off);

    if (lane == 0) {
        float h = acc + b[row];
        if (ACT == 1)      h = tanhf(h);
        else if (ACT == 2) h = h - tanhf(h);
        y[row] = h;
    }
}

// ---------------------------------------------------------------------------
// pdist: out[i*1024 + j] = || a[i,:] - a[j,:] ||_2   (a: [1024, DIMS])
// ---------------------------------------------------------------------------
template<int DIMS>
__global__ void __launch_bounds__(256) pdist_kernel(const float* __restrict__ a,
                                                    float* __restrict__ out)
{
    __shared__ float s[NB * DIMS];
    for (int t = threadIdx.x; t < NB * DIMS; t += 256) s[t] = a[t];
    __syncthreads();

    const int idx = blockIdx.x * 256 + threadIdx.x;   // 0 .. 1024*1024-1
    const int i = idx >> 10;
    const int j = idx & (NB - 1);

    float d2 = 0.f;
    #pragma unroll
    for (int k = 0; k < DIMS; ++k) {
        float d = s[i * DIMS + k] - s[j * DIMS + k];
        d2 = fmaf(d, d, d2);
    }
    out[idx] = sqrtf(d2);
}

// ---------------------------------------------------------------------------
// kernel_launch: encoder (4 GEMV) -> pdists -> decoder (4 GEMV)
// output layout: [output(3072) | in_diff(1024^2) | lat_diff(1024^2) | lat_repr(2048)]
// ---------------------------------------------------------------------------
extern "C" void kernel_launch(void* const* d_in, const int* in_sizes, int n_in,
                              void* d_out, int out_size)
{
    (void)in_sizes; (void)n_in; (void)out_size;

    const float* x   = (const float*)d_in[0];
    const float* ew1 = (const float*)d_in[1];
    const float* eb1 = (const float*)d_in[2];
    const float* ew2 = (const float*)d_in[3];
    const float* eb2 = (const float*)d_in[4];
    const float* ew3 = (const float*)d_in[5];
    const float* eb3 = (const float*)d_in[6];
    const float* ew4 = (const float*)d_in[7];
    const float* eb4 = (const float*)d_in[8];
    const float* dw1 = (const float*)d_in[9];
    const float* db1 = (const float*)d_in[10];
    const float* dw2 = (const float*)d_in[11];
    const float* db2 = (const float*)d_in[12];
    const float* dw3 = (const float*)d_in[13];
    const float* db3 = (const float*)d_in[14];
    const float* dw4 = (const float*)d_in[15];
    const float* db4 = (const float*)d_in[16];

    float* out      = (float*)d_out;
    float* out_main = out;                          // 3072
    float* out_ind  = out + AA;                     // 1024*1024
    float* out_lat  = out + AA + NB * NB;           // 1024*1024
    float* y        = out + AA + 2 * NB * NB;       // 2048 (lat_repr / encoder out)

    float *buf0, *buf1;
    cudaGetSymbolAddress((void**)&buf0, g_buf0);
    cudaGetSymbolAddress((void**)&buf1, g_buf1);

    // in_data pdist depends only on x — issue first
    pdist_kernel<3><<<(NB * NB) / 256, 256>>>(x, out_ind);

    // encoder
    gemv_kernel<1, AA><<<AA / 8, 256>>>(ew1, x,    eb1, buf0);
    gemv_kernel<1, AA><<<AA / 8, 256>>>(ew2, buf0, eb2, buf1);
    gemv_kernel<0, AA><<<AA / 8, 256>>>(ew3, buf1, eb3, buf0);
    gemv_kernel<2, AA><<<DD / 8, 256>>>(ew4, buf0, eb4, y);    // tanhshrink -> lat_repr

    // latent pdist
    pdist_kernel<2><<<(NB * NB) / 256, 256>>>(y, out_lat);

    // decoder (final layer fuses the output tanh)
    gemv_kernel<1, DD><<<AA / 8, 256>>>(dw1, y,    db1, buf0);
    gemv_kernel<1, AA><<<AA / 8, 256>>>(dw2, buf0, db2, buf1);
    gemv_kernel<0, AA><<<AA / 8, 256>>>(dw3, buf1, db3, buf0);
    gemv_kernel<1, AA><<<AA / 8, 256>>>(dw4, buf0, db4, out_main);
}

// round 2
// speedup vs baseline: 1.2560x; 1.2560x over previous
#include <cuda_runtime.h>
#include <math.h>

#define AA 3072   // A = BS * IA
#define DD 2048   // D = BS * (IA-1)
#define NB 1024   // BS

// scratch ping-pong buffers (no device allocation allowed)
__device__ float g_buf0[AA];
__device__ float g_buf1[AA];

// ---------------------------------------------------------------------------
// GEMV, block-per-row: y[row] = act( dot(W[row,:], x) + b[row] )
// 256 threads per row; each thread does COLS/1024 float4 FMAs; block reduce.
// ACT: 0 = none, 1 = tanh, 2 = tanhshrink (h - tanh(h))
// ---------------------------------------------------------------------------
template<int ACT, int COLS>
__global__ void __launch_bounds__(256) gemv_bpr(const float* __restrict__ W,
                                                const float* __restrict__ x,
                                                const float* __restrict__ b,
                                                float* __restrict__ y)
{
    const int row = blockIdx.x;
    const float4* __restrict__ W4 =
        reinterpret_cast<const float4*>(W + (size_t)row * COLS);
    const float4* __restrict__ x4 = reinterpret_cast<const float4*>(x);

    constexpr int N4 = COLS / 4;     // 768 or 512
    constexpr int IT = N4 / 256;     // 3 or 2

    // front-batched independent loads (high MLP)
    float4 w[IT], v[IT];
    #pragma unroll
    for (int k = 0; k < IT; ++k) {
        w[k] = W4[threadIdx.x + k * 256];
        v[k] = x4[threadIdx.x + k * 256];
    }
    float acc = 0.f;
    #pragma unroll
    for (int k = 0; k < IT; ++k) {
        acc = fmaf(w[k].x, v[k].x, acc);
        acc = fmaf(w[k].y, v[k].y, acc);
        acc = fmaf(w[k].z, v[k].z, acc);
        acc = fmaf(w[k].w, v[k].w, acc);
    }

    // warp reduce
    #pragma unroll
    for (int off = 16; off; off >>= 1)
        acc += __shfl_xor_sync(0xFFFFFFFFu, acc, off);

    __shared__ float sp[8];
    if ((threadIdx.x & 31) == 0) sp[threadIdx.x >> 5] = acc;
    __syncthreads();

    if (threadIdx.x < 32) {
        float s = (threadIdx.x < 8) ? sp[threadIdx.x] : 0.f;
        #pragma unroll
        for (int off = 4; off; off >>= 1)
            s += __shfl_xor_sync(0xFFFFFFFFu, s, off);
        if (threadIdx.x == 0) {
            float h = s + b[row];
            if (ACT == 1)      h = tanhf(h);
            else if (ACT == 2) h = h - tanhf(h);
            y[row] = h;
        }
    }
}

// ---------------------------------------------------------------------------
// pdist: out[i*1024 + j] = || a[i,:] - a[j,:] ||_2   (a: [1024, DIMS])
// ---------------------------------------------------------------------------
template<int DIMS>
__global__ void __launch_bounds__(256) pdist_kernel(const float* __restrict__ a,
                                                    float* __restrict__ out)
{
    __shared__ float s[NB * DIMS];
    for (int t = threadIdx.x; t < NB * DIMS; t += 256) s[t] = a[t];
    __syncthreads();

    const int idx = blockIdx.x * 256 + threadIdx.x;   // 0 .. 1024*1024-1
    const int i = idx >> 10;
    const int j = idx & (NB - 1);

    float d2 = 0.f;
    #pragma unroll
    for (int k = 0; k < DIMS; ++k) {
        float d = s[i * DIMS + k] - s[j * DIMS + k];
        d2 = fmaf(d, d, d2);
    }
    out[idx] = sqrtf(d2);
}

// ---------------------------------------------------------------------------
// kernel_launch: encoder (4 GEMV) -> pdists -> decoder (4 GEMV)
// output layout: [output(3072) | in_diff(1024^2) | lat_diff(1024^2) | lat_repr(2048)]
// ---------------------------------------------------------------------------
extern "C" void kernel_launch(void* const* d_in, const int* in_sizes, int n_in,
                              void* d_out, int out_size)
{
    (void)in_sizes; (void)n_in; (void)out_size;

    const float* x   = (const float*)d_in[0];
    const float* ew1 = (const float*)d_in[1];
    const float* eb1 = (const float*)d_in[2];
    const float* ew2 = (const float*)d_in[3];
    const float* eb2 = (const float*)d_in[4];
    const float* ew3 = (const float*)d_in[5];
    const float* eb3 = (const float*)d_in[6];
    const float* ew4 = (const float*)d_in[7];
    const float* eb4 = (const float*)d_in[8];
    const float* dw1 = (const float*)d_in[9];
    const float* db1 = (const float*)d_in[10];
    const float* dw2 = (const float*)d_in[11];
    const float* db2 = (const float*)d_in[12];
    const float* dw3 = (const float*)d_in[13];
    const float* db3 = (const float*)d_in[14];
    const float* dw4 = (const float*)d_in[15];
    const float* db4 = (const float*)d_in[16];

    float* out      = (float*)d_out;
    float* out_main = out;                          // 3072
    float* out_ind  = out + AA;                     // 1024*1024
    float* out_lat  = out + AA + NB * NB;           // 1024*1024
    float* y        = out + AA + 2 * NB * NB;       // 2048 (lat_repr / encoder out)

    float *buf0, *buf1;
    cudaGetSymbolAddress((void**)&buf0, g_buf0);
    cudaGetSymbolAddress((void**)&buf1, g_buf1);

    // in_data pdist depends only on x — issue first
    pdist_kernel<3><<<(NB * NB) / 256, 256>>>(x, out_ind);

    // encoder
    gemv_bpr<1, AA><<<AA, 256>>>(ew1, x,    eb1, buf0);
    gemv_bpr<1, AA><<<AA, 256>>>(ew2, buf0, eb2, buf1);
    gemv_bpr<0, AA><<<AA, 256>>>(ew3, buf1, eb3, buf0);
    gemv_bpr<2, AA><<<DD, 256>>>(ew4, buf0, eb4, y);    // tanhshrink -> lat_repr

    // latent pdist
    pdist_kernel<2><<<(NB * NB) / 256, 256>>>(y, out_lat);

    // decoder (final layer fuses the output tanh)
    gemv_bpr<1, DD><<<AA, 256>>>(dw1, y,    db1, buf0);
    gemv_bpr<1, AA><<<AA, 256>>>(dw2, buf0, db2, buf1);
    gemv_bpr<0, AA><<<AA, 256>>>(dw3, buf1, db3, buf0);
    gemv_bpr<1, AA><<<AA, 256>>>(dw4, buf0, db4, out_main);
}

// round 3
// speedup vs baseline: 1.2686x; 1.0101x over previous
#include <cuda_runtime.h>
#include <math.h>

#define AA 3072   // A = BS * IA
#define DD 2048   // D = BS * (IA-1)
#define NB 1024   // BS

// scratch ping-pong buffers (no device allocation allowed)
__device__ float g_buf0[AA];
__device__ float g_buf1[AA];

// ---------------------------------------------------------------------------
// GEMV, 4 rows per block: y[row] = act( dot(W[row,:], x) + b[row] )
// 256 threads; x float4s loaded ONCE into regs, reused for 4 rows.
// 12 (or 8) front-batched W LDG.128 per thread -> high DRAM MLP.
// ACT: 0 = none, 1 = tanh, 2 = tanhshrink (h - tanh(h))
// ---------------------------------------------------------------------------
template<int ACT, int COLS>
__global__ void __launch_bounds__(256) gemv_r4(const float* __restrict__ W,
                                               const float* __restrict__ x,
                                               const float* __restrict__ b,
                                               float* __restrict__ y)
{
    constexpr int N4 = COLS / 4;     // 768 or 512
    constexpr int IT = N4 / 256;     // 3 or 2
    const int row0 = blockIdx.x * 4;

    const float4* __restrict__ x4 = reinterpret_cast<const float4*>(x);

    // x loads (L1/L2-resident)
    float4 v[IT];
    #pragma unroll
    for (int k = 0; k < IT; ++k) v[k] = x4[threadIdx.x + k * 256];

    // front-batched W loads: 4 rows x IT float4, all independent
    float4 w[4][IT];
    #pragma unroll
    for (int r = 0; r < 4; ++r) {
        const float4* __restrict__ W4 =
            reinterpret_cast<const float4*>(W + (size_t)(row0 + r) * COLS);
        #pragma unroll
        for (int k = 0; k < IT; ++k)
            w[r][k] = W4[threadIdx.x + k * 256];
    }

    float acc[4];
    #pragma unroll
    for (int r = 0; r < 4; ++r) {
        float a = 0.f;
        #pragma unroll
        for (int k = 0; k < IT; ++k) {
            a = fmaf(w[r][k].x, v[k].x, a);
            a = fmaf(w[r][k].y, v[k].y, a);
            a = fmaf(w[r][k].z, v[k].z, a);
            a = fmaf(w[r][k].w, v[k].w, a);
        }
        acc[r] = a;
    }

    // warp reduce each row accumulator
    #pragma unroll
    for (int r = 0; r < 4; ++r)
        #pragma unroll
        for (int off = 16; off; off >>= 1)
            acc[r] += __shfl_xor_sync(0xFFFFFFFFu, acc[r], off);

    // sp[warp*4 + r]
    __shared__ float sp[32];
    const int lane = threadIdx.x & 31;
    const int warp = threadIdx.x >> 5;
    if (lane == 0) {
        #pragma unroll
        for (int r = 0; r < 4; ++r) sp[warp * 4 + r] = acc[r];
    }
    __syncthreads();

    if (threadIdx.x < 32) {
        // thread t holds partial for (warp = t>>2, row = t&3)
        float s = sp[threadIdx.x];
        s += __shfl_xor_sync(0xFFFFFFFFu, s, 4);
        s += __shfl_xor_sync(0xFFFFFFFFu, s, 8);
        s += __shfl_xor_sync(0xFFFFFFFFu, s, 16);
        if (threadIdx.x < 4) {
            float h = s + b[row0 + threadIdx.x];
            if (ACT == 1)      h = tanhf(h);
            else if (ACT == 2) h = h - tanhf(h);
            y[row0 + threadIdx.x] = h;
        }
    }
}

// ---------------------------------------------------------------------------
// pdist: out[i*1024 + j] = || a[i,:] - a[j,:] ||_2   (a: [1024, DIMS])
// ---------------------------------------------------------------------------
template<int DIMS>
__global__ void __launch_bounds__(256) pdist_kernel(const float* __restrict__ a,
                                                    float* __restrict__ out)
{
    __shared__ float s[NB * DIMS];
    for (int t = threadIdx.x; t < NB * DIMS; t += 256) s[t] = a[t];
    __syncthreads();

    const int idx = blockIdx.x * 256 + threadIdx.x;   // 0 .. 1024*1024-1
    const int i = idx >> 10;
    const int j = idx & (NB - 1);

    float d2 = 0.f;
    #pragma unroll
    for (int k = 0; k < DIMS; ++k) {
        float d = s[i * DIMS + k] - s[j * DIMS + k];
        d2 = fmaf(d, d, d2);
    }
    out[idx] = sqrtf(d2);
}

// ---------------------------------------------------------------------------
// kernel_launch: encoder (4 GEMV) -> pdists -> decoder (4 GEMV)
// output layout: [output(3072) | in_diff(1024^2) | lat_diff(1024^2) | lat_repr(2048)]
// ---------------------------------------------------------------------------
extern "C" void kernel_launch(void* const* d_in, const int* in_sizes, int n_in,
                              void* d_out, int out_size)
{
    (void)in_sizes; (void)n_in; (void)out_size;

    const float* x   = (const float*)d_in[0];
    const float* ew1 = (const float*)d_in[1];
    const float* eb1 = (const float*)d_in[2];
    const float* ew2 = (const float*)d_in[3];
    const float* eb2 = (const float*)d_in[4];
    const float* ew3 = (const float*)d_in[5];
    const float* eb3 = (const float*)d_in[6];
    const float* ew4 = (const float*)d_in[7];
    const float* eb4 = (const float*)d_in[8];
    const float* dw1 = (const float*)d_in[9];
    const float* db1 = (const float*)d_in[10];
    const float* dw2 = (const float*)d_in[11];
    const float* db2 = (const float*)d_in[12];
    const float* dw3 = (const float*)d_in[13];
    const float* db3 = (const float*)d_in[14];
    const float* dw4 = (const float*)d_in[15];
    const float* db4 = (const float*)d_in[16];

    float* out      = (float*)d_out;
    float* out_main = out;                          // 3072
    float* out_ind  = out + AA;                     // 1024*1024
    float* out_lat  = out + AA + NB * NB;           // 1024*1024
    float* y        = out + AA + 2 * NB * NB;       // 2048 (lat_repr / encoder out)

    float *buf0, *buf1;
    cudaGetSymbolAddress((void**)&buf0, g_buf0);
    cudaGetSymbolAddress((void**)&buf1, g_buf1);

    // in_data pdist depends only on x — issue first
    pdist_kernel<3><<<(NB * NB) / 256, 256>>>(x, out_ind);

    // encoder
    gemv_r4<1, AA><<<AA / 4, 256>>>(ew1, x,    eb1, buf0);
    gemv_r4<1, AA><<<AA / 4, 256>>>(ew2, buf0, eb2, buf1);
    gemv_r4<0, AA><<<AA / 4, 256>>>(ew3, buf1, eb3, buf0);
    gemv_r4<2, AA><<<DD / 4, 256>>>(ew4, buf0, eb4, y);    // tanhshrink -> lat_repr

    // latent pdist
    pdist_kernel<2><<<(NB * NB) / 256, 256>>>(y, out_lat);

    // decoder (final layer fuses the output tanh)
    gemv_r4<1, DD><<<AA / 4, 256>>>(dw1, y,    db1, buf0);
    gemv_r4<1, AA><<<AA / 4, 256>>>(dw2, buf0, db2, buf1);
    gemv_r4<0, AA><<<AA / 4, 256>>>(dw3, buf1, db3, buf0);
    gemv_r4<1, AA><<<AA / 4, 256>>>(dw4, buf0, db4, out_main);
}